// round 17
// baseline (speedup 1.0000x reference)
#include <cuda_runtime.h>
#include <cuda_bf16.h>

// Balloon-Windkessel BOLD, 1000 Euler steps — parallel-in-time, v6.
// 256 threads (8 warps), thread t owns steps 4t..4t+3.
// vs v5: prolog MUFU cut 32 -> 8 per thread. Inside a chunk:
//  - (rc,rs) advance by the EXACT discrete eigen-rotation (M00=1-h/2,
//    M01=sqrt(3)h/2): f_j, s_j are exact, FMA-only.
//  - E(f_j), f_j^alpha, f_j^(2a-2) Taylor-updated from j=0 values
//    (2-Newton reciprocal + 2nd-order exp series; coeff err ~1e-7).
// 3 scan passes (2 Newton + fused final-Newton-v/q) keep exact MUFU u.

#define N_STEPS 1000
#define NT      256
#define CHUNK   4
#define NW      (NT/32)
#define DT      0.01f
#define RHO     0.34f
#define ALPHA   0.32f

#define LOG2R   (-0.0071769220f)   // log2(sqrt(1 - h + h^2)), h = 0.01
#define THETA   (0.0087035531f)    // atan2(sqrt(3)/2*h, 1 - h/2)
#define INVSQ3  (0.57735026919f)
#define TWOSQ3  (1.15470053838f)   // 2/sqrt(3)
#define L66     (-0.5994621118f)   // log2(0.66)
#define A2      (ALPHA*ALPHA)      // 0.1024
#define M00     0.995f             // 1 - h/2 (exact eigen rotation)
#define M01     0.0086602540f      // sqrt(3)/2 * h
#define LN2     0.69314718f
#define LN2SQ2  0.24022651f        // ln2^2 / 2

#define YC   0.0972f
#define YK1  0.0476f
#define YK2  0.04f
#define YK3  0.0096f

__device__ __forceinline__ float ex2a(float x){ float r; asm("ex2.approx.f32 %0,%1;":"=f"(r):"f"(x)); return r; }
__device__ __forceinline__ float lg2a(float x){ float r; asm("lg2.approx.f32 %0,%1;":"=f"(r):"f"(x)); return r; }
__device__ __forceinline__ float sina(float x){ float r; asm("sin.approx.f32 %0,%1;":"=f"(r):"f"(x)); return r; }
__device__ __forceinline__ float cosa(float x){ float r; asm("cos.approx.f32 %0,%1;":"=f"(r):"f"(x)); return r; }
__device__ __forceinline__ float rcpa(float x){ float r; asm("rcp.approx.f32 %0,%1;":"=f"(r):"f"(x)); return r; }

// Block scan of affine maps over 8 warps; returns inclusive and exclusive.
__device__ __forceinline__ void scan1(float& A, float& B, float& exA, float& exB,
                                      int lane, int warp, float* sA, float* sB) {
    #pragma unroll
    for (int d = 1; d < 32; d <<= 1) {
        float pA = __shfl_up_sync(0xffffffffu, A, d);
        float pB = __shfl_up_sync(0xffffffffu, B, d);
        if (lane >= d) { B = fmaf(A, pB, B); A = A * pA; }
    }
    if (lane == 31) { sA[warp] = A; sB[warp] = B; }
    __syncthreads();
    if (warp == 0) {
        float wA = (lane < NW) ? sA[lane] : 1.0f;
        float wB = (lane < NW) ? sB[lane] : 0.0f;
        #pragma unroll
        for (int d = 1; d < NW; d <<= 1) {
            float pA = __shfl_up_sync(0xffffffffu, wA, d);
            float pB = __shfl_up_sync(0xffffffffu, wB, d);
            if (lane >= d) { wB = fmaf(wA, pB, wB); wA = wA * pA; }
        }
        if (lane < NW) { sA[lane] = wA; sB[lane] = wB; }
    }
    __syncthreads();
    float pA = 1.0f, pB = 0.0f;
    if (warp > 0) { pA = sA[warp - 1]; pB = sB[warp - 1]; }
    B = fmaf(A, pB, B);
    A = A * pA;
    exA = __shfl_up_sync(0xffffffffu, A, 1);
    exB = __shfl_up_sync(0xffffffffu, B, 1);
    if (lane == 0) { exA = pA; exB = pB; }
}

// Dual affine block scan; returns exclusive prefixes for both maps.
__device__ __forceinline__ void scan2(float& A, float& B, float& C, float& D,
                                      float& exA, float& exB, float& exC, float& exD,
                                      int lane, int warp,
                                      float* sA, float* sB, float* sC, float* sD) {
    #pragma unroll
    for (int d = 1; d < 32; d <<= 1) {
        float pA = __shfl_up_sync(0xffffffffu, A, d);
        float pB = __shfl_up_sync(0xffffffffu, B, d);
        float pC = __shfl_up_sync(0xffffffffu, C, d);
        float pD = __shfl_up_sync(0xffffffffu, D, d);
        if (lane >= d) {
            B = fmaf(A, pB, B); A = A * pA;
            D = fmaf(C, pD, D); C = C * pC;
        }
    }
    if (lane == 31) { sA[warp] = A; sB[warp] = B; sC[warp] = C; sD[warp] = D; }
    __syncthreads();
    if (warp == 0) {
        float wA = (lane < NW) ? sA[lane] : 1.0f;
        float wB = (lane < NW) ? sB[lane] : 0.0f;
        float wC = (lane < NW) ? sC[lane] : 1.0f;
        float wD = (lane < NW) ? sD[lane] : 0.0f;
        #pragma unroll
        for (int d = 1; d < NW; d <<= 1) {
            float pA = __shfl_up_sync(0xffffffffu, wA, d);
            float pB = __shfl_up_sync(0xffffffffu, wB, d);
            float pC = __shfl_up_sync(0xffffffffu, wC, d);
            float pD = __shfl_up_sync(0xffffffffu, wD, d);
            if (lane >= d) {
                wB = fmaf(wA, pB, wB); wA = wA * pA;
                wD = fmaf(wC, pD, wD); wC = wC * pC;
            }
        }
        if (lane < NW) { sA[lane] = wA; sB[lane] = wB; sC[lane] = wC; sD[lane] = wD; }
    }
    __syncthreads();
    float pA = 1.0f, pB = 0.0f, pC = 1.0f, pD = 0.0f;
    if (warp > 0) { pA = sA[warp-1]; pB = sB[warp-1]; pC = sC[warp-1]; pD = sD[warp-1]; }
    B = fmaf(A, pB, B); A = A * pA;
    D = fmaf(C, pD, D); C = C * pC;
    exA = __shfl_up_sync(0xffffffffu, A, 1);
    exB = __shfl_up_sync(0xffffffffu, B, 1);
    exC = __shfl_up_sync(0xffffffffu, C, 1);
    exD = __shfl_up_sync(0xffffffffu, D, 1);
    if (lane == 0) { exA = pA; exB = pB; exC = pC; exD = pD; }
}

__global__ void __launch_bounds__(NT, 1)
bold_pits_kernel(const float* __restrict__ mtt_ptr, float* __restrict__ y_out) {
    __shared__ float s0[NW], s1[NW], s2[NW], s3[NW], s4[NW], s5[NW], s6[NW], s7[NW];

    const int tid  = threadIdx.x;
    const int lane = tid & 31;
    const int warp = tid >> 5;
    const int base = tid * CHUNK;
    const bool active = (base < N_STEPS);      // 250 threads fully active

    const float mtt = mtt_ptr[0];
    const float dtm = DT / mtt;

    // ---- prolog: exact eigen-rotation + j=0 MUFU + in-chunk Taylor --------
    float a[CHUNK], g[CHUNK], vk[CHUNK];
    #pragma unroll
    for (int j = 0; j < CHUNK; ++j) { a[j] = 0.0f; g[j] = 0.0f; vk[j] = 1.0f; }
    if (active) {
        float tf  = (float)base;
        float rp  = ex2a(LOG2R * tf);
        float ang = THETA * tf;
        float rc  = rp * cosa(ang);            // rp * cos
        float rs  = rp * sina(ang);            // rp * sin

        float fj[CHUNK], sj[CHUNK];
        #pragma unroll
        for (int j = 0; j < CHUNK; ++j) {
            fj[j] = 2.0f - fmaf(INVSQ3, rs, rc);
            sj[j] = TWOSQ3 * rs;
            float rc2 = fmaf(M00, rc, -M01 * rs);   // exact eigen step
            float rs2 = fmaf(M01, rc,  M00 * rs);
            rc = rc2; rs = rs2;
        }

        float f0   = fj[0];
        float rf0  = rcpa(f0);
        float P0   = ex2a(L66 * rf0);          // 0.66^(1/f0)
        float lgf0 = lg2a(f0);
        float fa0  = ex2a(ALPHA * lgf0);       // f0^alpha
        float fp0  = ex2a((2.0f*ALPHA - 2.0f) * lgf0);  // f0^(2a-2)

        #pragma unroll
        for (int j = 0; j < CHUNK; ++j) {
            // 1/f_j via 2 Newton iterations from rf0 (err ~1e-8)
            float r1 = rf0 * (2.0f - fj[j] * rf0);
            float rj = r1  * (2.0f - fj[j] * r1);
            // P_j = P0 * 2^(L66 * (1/f_j - 1/f_0)), 2nd-order series
            float w  = L66 * (rj - rf0);
            float Pj = P0 * fmaf(w, fmaf(LN2SQ2, w, LN2), 1.0f);
            a[j] = dtm * fj[j];
            g[j] = (dtm / RHO) * fj[j] * (1.0f - Pj);
            // warm start: fa_j, fp_j by 2nd-order Taylor in eps = f_j/f0 - 1
            float eps = fmaf(fj[j], rf0, -1.0f);
            float faj = fa0 * fmaf(eps, fmaf(-0.1088f, eps, 0.32f), 1.0f);
            float fpj = fp0 * fmaf(eps, fmaf(1.6048f, eps, -1.36f), 1.0f);
            vk[j] = fmaf(-mtt * A2 * sj[j], fpj, faj);
        }
    }

    // ---- Passes 1 & 2: Newton sweeps for v (exact MUFU u) -----------------
    #pragma unroll
    for (int pass = 0; pass < 2; ++pass) {
        float As[CHUNK], Bs[CHUNK];
        float A = 1.0f, B = 0.0f;
        if (active) {
            #pragma unroll
            for (int j = 0; j < CHUNK; ++j) {
                float u  = ex2a(2.125f * lg2a(vk[j]));
                float du = dtm * u;
                As[j] = fmaf(-3.125f, du, 1.0f);
                Bs[j] = fmaf(2.125f * vk[j], du, a[j]);
                B = fmaf(As[j], B, Bs[j]);
                A = A * As[j];
            }
        } else {
            #pragma unroll
            for (int j = 0; j < CHUNK; ++j) { As[j] = 1.0f; Bs[j] = 0.0f; }
        }
        float exA, exB;
        if (pass) scan1(A, B, exA, exB, lane, warp, s2, s3);
        else      scan1(A, B, exA, exB, lane, warp, s0, s1);
        float v = exA + exB;
        if (active) {
            #pragma unroll
            for (int j = 0; j < CHUNK; ++j) {
                vk[j] = v;
                v = fmaf(As[j], v, Bs[j]);
            }
        }
    }

    // ---- Pass 3: fused final Newton (v) + exact q-scan --------------------
    float Avs[CHUNK], Bvs[CHUNK], Aqs[CHUNK], Bqs[CHUNK];
    float Av = 1.0f, Bv = 0.0f, Aq = 1.0f, Bq = 0.0f;
    if (active) {
        #pragma unroll
        for (int j = 0; j < CHUNK; ++j) {
            float u  = ex2a(2.125f * lg2a(vk[j]));
            float du = dtm * u;
            Avs[j] = fmaf(-3.125f, du, 1.0f);
            Bvs[j] = fmaf(2.125f * vk[j], du, a[j]);
            Aqs[j] = 1.0f - du;
            Bqs[j] = g[j];
            Bv = fmaf(Avs[j], Bv, Bvs[j]); Av = Av * Avs[j];
            Bq = fmaf(Aqs[j], Bq, Bqs[j]); Aq = Aq * Aqs[j];
        }
    } else {
        #pragma unroll
        for (int j = 0; j < CHUNK; ++j) { Avs[j]=1.0f; Bvs[j]=0.0f; Aqs[j]=1.0f; Bqs[j]=0.0f; }
    }
    float exAv, exBv, exAq, exBq;
    scan2(Av, Bv, Aq, Bq, exAv, exBv, exAq, exBq, lane, warp, s4, s5, s6, s7);

    // ---- replay + BOLD readout, one float4 store per thread ---------------
    if (active) {
        float v = exAv + exBv;
        float q = exAq + exBq;
        float yv[CHUNK];
        #pragma unroll
        for (int j = 0; j < CHUNK; ++j) {
            v = fmaf(Avs[j], v, Bvs[j]);
            q = fmaf(Aqs[j], q, Bqs[j]);
            float yt = fmaf(-YK1, q, YC);
            yt = fmaf(-YK3, v, yt);
            yt = fmaf(-YK2, q * rcpa(v), yt);
            yv[j] = yt;
        }
        float4 y4;
        y4.x = yv[0]; y4.y = yv[1]; y4.z = yv[2]; y4.w = yv[3];
        reinterpret_cast<float4*>(y_out)[tid] = y4;
    }
}

extern "C" void kernel_launch(void* const* d_in, const int* in_sizes, int n_in,
                              void* d_out, int out_size) {
    const float* mtt = (const float*)d_in[0];
    float* y = (float*)d_out;
    bold_pits_kernel<<<1, NT>>>(mtt, y);
}